// round 5
// baseline (speedup 1.0000x reference)
#include <cuda_runtime.h>
#include <math.h>

// Problem dims (fixed by dataset)
#define TSTEPS 16
#define NNODES 4096
#define RDIM   256
#define CDIM   32

// Scratch (static device globals — no allocation)
__device__ float g_Mz[RDIM * RDIM];              // Wz + Uz
__device__ float g_Mr[RDIM * RDIM];              // Wr + Ur
__device__ float g_QT[TSTEPS * RDIM * CDIM];     // evolved weights Q_t
__device__ float g_Y [TSTEPS * NNODES * CDIM];   // Y_t = X_t @ Q_t

// ---------------------------------------------------------------------------
// Prep: fold gate weight pairs (z and r gates use W@Q + U@Q = (W+U)@Q)
// ---------------------------------------------------------------------------
__global__ void prep_fold(const float* __restrict__ Wz, const float* __restrict__ Uz,
                          const float* __restrict__ Wr, const float* __restrict__ Ur) {
    int i = blockIdx.x * blockDim.x + threadIdx.x;   // grid covers exactly R*R
    g_Mz[i] = Wz[i] + Uz[i];
    g_Mr[i] = Wr[i] + Ur[i];
}

// ---------------------------------------------------------------------------
// GRU evolution of Q [256,32] over 16 steps.
// Column-separable: block b owns column b. 256 threads = one per row.
// All matmuls are dot(weight_row_r, q_column) with q in smem.
// ---------------------------------------------------------------------------
__global__ void __launch_bounds__(RDIM) gru_kernel(const float* __restrict__ Q0,
                                                   const float* __restrict__ Wh,
                                                   const float* __restrict__ Uh) {
    const int c = blockIdx.x;     // column 0..31
    const int r = threadIdx.x;    // row    0..255

    __shared__ float q[RDIM];
    __shared__ float rq[RDIM];

    q[r] = Q0[r * CDIM + c];
    __syncthreads();

    const float4* Mz4 = (const float4*)(g_Mz + r * RDIM);
    const float4* Mr4 = (const float4*)(g_Mr + r * RDIM);
    const float4* Wh4 = (const float4*)(Wh + (long)r * RDIM);
    const float4* Uh4 = (const float4*)(Uh + (long)r * RDIM);

    for (int t = 0; t < TSTEPS; t++) {
        // Gates z, r: dot of folded weight rows with q
        float sz = 0.f, sr = 0.f;
        #pragma unroll 8
        for (int k4 = 0; k4 < RDIM / 4; k4++) {
            float4 wz = Mz4[k4];
            float4 wr = Mr4[k4];
            int k = k4 * 4;
            float q0 = q[k], q1 = q[k + 1], q2 = q[k + 2], q3 = q[k + 3];
            sz += wz.x * q0 + wz.y * q1 + wz.z * q2 + wz.w * q3;
            sr += wr.x * q0 + wr.y * q1 + wr.z * q2 + wr.w * q3;
        }
        float z  = 1.f / (1.f + expf(-sz));
        float rg = 1.f / (1.f + expf(-sr));

        rq[r] = rg * q[r];
        __syncthreads();          // rq fully written before candidate matmul

        // Candidate h = tanh(Wh@q + Uh@rq)
        float sh = 0.f;
        #pragma unroll 8
        for (int k4 = 0; k4 < RDIM / 4; k4++) {
            float4 wh = Wh4[k4];
            float4 uh = Uh4[k4];
            int k = k4 * 4;
            sh += wh.x * q[k]      + wh.y * q[k + 1]  + wh.z * q[k + 2]  + wh.w * q[k + 3];
            sh += uh.x * rq[k]     + uh.y * rq[k + 1] + uh.z * rq[k + 2] + uh.w * rq[k + 3];
        }
        float h  = tanhf(sh);
        float qr = q[r];
        float qn = (1.f - z) * qr + z * h;

        __syncthreads();          // everyone done reading q before overwrite
        q[r] = qn;
        g_QT[t * RDIM * CDIM + r * CDIM + c] = qn;
        __syncthreads();          // q update visible before next step
    }
}

// ---------------------------------------------------------------------------
// Packed fp32x2 FMA helpers (Blackwell-only PTX; 2x fp32 FMA throughput)
// ---------------------------------------------------------------------------
__device__ __forceinline__ void ffma2(unsigned long long& d, unsigned long long a,
                                      unsigned long long b) {
    asm("fma.rn.f32x2 %0, %1, %2, %0;" : "+l"(d) : "l"(a), "l"(b));
}
__device__ __forceinline__ unsigned long long splat2(float x) {
    unsigned long long r;
    asm("mov.b64 %0, {%1, %1};" : "=l"(r) : "f"(x));
    return r;
}

// ---------------------------------------------------------------------------
// GEMM: C[t] = (relu?)(A[t] @ B[t]), A [M x K] row-major, B [K x 32], C [M x 32]
// BM=128, BN=32, BK=32, 128 threads, micro-tile 8m x 4n, f32x2 accumulators.
// A staged transposed in smem (As[k][m]) so m-pairs pack into f32x2 for free.
// Register-staged double-buffered pipeline over k-tiles.
// grid = (M/128, T)
// ---------------------------------------------------------------------------
__global__ void __launch_bounds__(128) gemm_n32(const float* __restrict__ Abase,
                                                const float* __restrict__ Bbase,
                                                float* __restrict__ Cbase,
                                                int K, long sAt, long sBt, long sCt,
                                                int relu) {
    __shared__ float As[2][32][132];   // [buf][k][m], padded row (132)
    __shared__ float Bs[2][32][32];    // [buf][k][n]

    const int t   = blockIdx.y;
    const int tid = threadIdx.x;
    const float* A  = Abase + (long)t * sAt + (long)blockIdx.x * 128 * K;
    const float* B  = Bbase + (long)t * sBt;
    float*       Cp = Cbase + (long)t * sCt + (long)blockIdx.x * 128 * CDIM;

    float4 aReg[8];
    float4 bReg[2];
    const int nt = K >> 5;

    auto loadT = [&](int kt) {
        #pragma unroll
        for (int i = 0; i < 8; i++) {
            int idx = tid + i * 128;           // 1024 float4 chunks of A tile
            int m   = idx >> 3;                // 0..127
            int k4  = idx & 7;                 // 0..7
            aReg[i] = *(const float4*)(A + (long)m * K + kt * 32 + k4 * 4);
        }
        #pragma unroll
        for (int i = 0; i < 2; i++) {
            int idx = tid + i * 128;           // 256 float4 chunks of B tile
            int kr  = idx >> 3;                // 0..31
            int c4  = idx & 7;                 // 0..7
            bReg[i] = *(const float4*)(B + (long)(kt * 32 + kr) * CDIM + c4 * 4);
        }
    };
    auto storeT = [&](int buf) {
        #pragma unroll
        for (int i = 0; i < 8; i++) {
            int idx = tid + i * 128;
            int m   = idx >> 3;
            int k4  = (idx & 7) * 4;
            As[buf][k4 + 0][m] = aReg[i].x;    // transpose: As[k][m]
            As[buf][k4 + 1][m] = aReg[i].y;
            As[buf][k4 + 2][m] = aReg[i].z;
            As[buf][k4 + 3][m] = aReg[i].w;
        }
        #pragma unroll
        for (int i = 0; i < 2; i++) {
            int idx = tid + i * 128;
            int kr  = idx >> 3;
            int c4  = (idx & 7) * 4;
            *(float4*)&Bs[buf][kr][c4] = bReg[i];
        }
    };

    unsigned long long acc[16];                // acc[mp*4+n] packs rows (2mp, 2mp+1)
    #pragma unroll
    for (int i = 0; i < 16; i++) acc[i] = 0ull;

    // Warp layout: tn = tid&7 (8 n-groups, broadcast b per warp), tm = tid>>3
    const int m0 = (tid >> 3) * 8;             // 16 m-groups * 8 rows = 128
    const int n0 = (tid & 7) * 4;              //  8 n-groups * 4 cols = 32

    loadT(0);
    storeT(0);
    __syncthreads();

    for (int kt = 0; kt < nt; kt++) {
        int buf = kt & 1;
        if (kt + 1 < nt) loadT(kt + 1);        // prefetch next tile into regs

        #pragma unroll
        for (int k = 0; k < 32; k++) {
            ulonglong2 A0 = *(const ulonglong2*)&As[buf][k][m0];       // rows m0..m0+3
            ulonglong2 A1 = *(const ulonglong2*)&As[buf][k][m0 + 4];   // rows m0+4..m0+7
            float4 bv = *(const float4*)&Bs[buf][k][n0];
            unsigned long long b0 = splat2(bv.x), b1 = splat2(bv.y);
            unsigned long long b2 = splat2(bv.z), b3 = splat2(bv.w);
            ffma2(acc[ 0], A0.x, b0); ffma2(acc[ 1], A0.x, b1);
            ffma2(acc[ 2], A0.x, b2); ffma2(acc[ 3], A0.x, b3);
            ffma2(acc[ 4], A0.y, b0); ffma2(acc[ 5], A0.y, b1);
            ffma2(acc[ 6], A0.y, b2); ffma2(acc[ 7], A0.y, b3);
            ffma2(acc[ 8], A1.x, b0); ffma2(acc[ 9], A1.x, b1);
            ffma2(acc[10], A1.x, b2); ffma2(acc[11], A1.x, b3);
            ffma2(acc[12], A1.y, b0); ffma2(acc[13], A1.y, b1);
            ffma2(acc[14], A1.y, b2); ffma2(acc[15], A1.y, b3);
        }

        if (kt + 1 < nt) {
            __syncthreads();                   // all done reading old buffer
            storeT(buf ^ 1);                   // commit prefetched tile
            __syncthreads();                   // new buffer visible
        }
    }

    // Epilogue: unpack f32x2 pairs, optional relu, vectorized store
    #pragma unroll
    for (int mp = 0; mp < 4; mp++) {
        float2 v0 = *(float2*)&acc[mp * 4 + 0];
        float2 v1 = *(float2*)&acc[mp * 4 + 1];
        float2 v2 = *(float2*)&acc[mp * 4 + 2];
        float2 v3 = *(float2*)&acc[mp * 4 + 3];
        float4 lo = make_float4(v0.x, v1.x, v2.x, v3.x);   // row m0+2mp
        float4 hi = make_float4(v0.y, v1.y, v2.y, v3.y);   // row m0+2mp+1
        if (relu) {
            lo.x = fmaxf(lo.x, 0.f); lo.y = fmaxf(lo.y, 0.f);
            lo.z = fmaxf(lo.z, 0.f); lo.w = fmaxf(lo.w, 0.f);
            hi.x = fmaxf(hi.x, 0.f); hi.y = fmaxf(hi.y, 0.f);
            hi.z = fmaxf(hi.z, 0.f); hi.w = fmaxf(hi.w, 0.f);
        }
        *(float4*)&Cp[(long)(m0 + mp * 2 + 0) * CDIM + n0] = lo;
        *(float4*)&Cp[(long)(m0 + mp * 2 + 1) * CDIM + n0] = hi;
    }
}

// ---------------------------------------------------------------------------
// Launch: prep -> GRU (all Q_t) -> Y_t = X_t @ Q_t -> out_t = relu(A_t @ Y_t)
// ---------------------------------------------------------------------------
extern "C" void kernel_launch(void* const* d_in, const int* in_sizes, int n_in,
                              void* d_out, int out_size) {
    const float* A  = (const float*)d_in[0];   // [1,16,4096,4096]
    const float* X  = (const float*)d_in[1];   // [16,4096,256]
    const float* Q0 = (const float*)d_in[2];   // [256,32]
    const float* Wz = (const float*)d_in[3];
    const float* Uz = (const float*)d_in[4];
    const float* Wr = (const float*)d_in[5];
    const float* Ur = (const float*)d_in[6];
    const float* Wh = (const float*)d_in[7];
    const float* Uh = (const float*)d_in[8];
    float* out = (float*)d_out;                // [16,4096,32]

    void *pQT = nullptr, *pY = nullptr;
    cudaGetSymbolAddress(&pQT, g_QT);
    cudaGetSymbolAddress(&pY,  g_Y);

    // 1. Fold z/r gate weights
    prep_fold<<<RDIM * RDIM / 256, 256>>>(Wz, Uz, Wr, Ur);

    // 2. Evolve Q over 16 steps (column-parallel, single launch)
    gru_kernel<<<CDIM, RDIM>>>(Q0, Wh, Uh);

    // 3. Y_t = X_t @ Q_t   (M=4096, K=256)
    gemm_n32<<<dim3(NNODES / 128, TSTEPS), 128>>>(
        X, (const float*)pQT, (float*)pY,
        RDIM,
        (long)NNODES * RDIM,        // X stride per t
        (long)RDIM * CDIM,          // Q_t stride per t
        (long)NNODES * CDIM,        // Y stride per t
        /*relu=*/0);

    // 4. out_t = relu(A_t @ Y_t)   (M=4096, K=4096) — the dominant phase
    gemm_n32<<<dim3(NNODES / 128, TSTEPS), 128>>>(
        A, (const float*)pY, out,
        NNODES,
        (long)NNODES * NNODES,      // A stride per t
        (long)NNODES * CDIM,        // Y stride per t
        (long)NNODES * CDIM,        // out stride per t
        /*relu=*/1);
}

// round 7
// speedup vs baseline: 3.6459x; 3.6459x over previous
#include <cuda_runtime.h>
#include <cuda_bf16.h>
#include <cstdint>
#include <math.h>

// Problem dims (fixed by dataset)
#define TSTEPS 16
#define NNODES 4096
#define RDIM   256
#define CDIM   32

// Scratch (static device globals — no allocation)
__device__ float g_Mz[RDIM * RDIM];                       // Wz + Uz
__device__ float g_Mr[RDIM * RDIM];                       // Wr + Ur
__device__ float g_QT[TSTEPS * RDIM * CDIM];              // evolved weights Q_t
__device__ unsigned short g_Yth[TSTEPS * CDIM * NNODES];  // Y^T hi bf16 [t][n][k]
__device__ unsigned short g_Ytl[TSTEPS * CDIM * NNODES];  // Y^T lo bf16 [t][n][k]

// ---------------------------------------------------------------------------
// Small PTX helpers
// ---------------------------------------------------------------------------
__device__ __forceinline__ uint32_t smem_u32(const void* p) {
    uint32_t a;
    asm("{ .reg .u64 t; cvta.to.shared.u64 t, %1; cvt.u32.u64 %0, t; }"
        : "=r"(a) : "l"(p));
    return a;
}
__device__ __forceinline__ uint32_t cvt_bf16x2(float hi, float lo) {
    uint32_t r;
    asm("cvt.rn.bf16x2.f32 %0, %1, %2;" : "=r"(r) : "f"(hi), "f"(lo));
    return r;
}
__device__ __forceinline__ void ldsm4(uint32_t* r, uint32_t a) {
    asm volatile("ldmatrix.sync.aligned.m8n8.x4.shared.b16 {%0,%1,%2,%3}, [%4];"
                 : "=r"(r[0]), "=r"(r[1]), "=r"(r[2]), "=r"(r[3]) : "r"(a));
}
__device__ __forceinline__ void mma16816(float* c, const uint32_t* a,
                                         uint32_t b0, uint32_t b1) {
    asm volatile(
        "mma.sync.aligned.m16n8k16.row.col.f32.bf16.bf16.f32 "
        "{%0,%1,%2,%3}, {%4,%5,%6,%7}, {%8,%9}, {%0,%1,%2,%3};"
        : "+f"(c[0]), "+f"(c[1]), "+f"(c[2]), "+f"(c[3])
        : "r"(a[0]), "r"(a[1]), "r"(a[2]), "r"(a[3]), "r"(b0), "r"(b1));
}

// ---------------------------------------------------------------------------
// Prep: fold gate weight pairs (z and r gates use W@Q + U@Q = (W+U)@Q)
// ---------------------------------------------------------------------------
__global__ void prep_fold(const float* __restrict__ Wz, const float* __restrict__ Uz,
                          const float* __restrict__ Wr, const float* __restrict__ Ur) {
    int i = blockIdx.x * blockDim.x + threadIdx.x;
    g_Mz[i] = Wz[i] + Uz[i];
    g_Mr[i] = Wr[i] + Ur[i];
}

// ---------------------------------------------------------------------------
// GRU evolution of Q [256,32] over 16 steps. Block = one column.
// Coalesced: warp-per-row matvec, lanes span K (contiguous 1KB), shfl-reduce.
// ---------------------------------------------------------------------------
__device__ __forceinline__ float dot4(float4 a, float4 b) {
    return a.x * b.x + a.y * b.y + a.z * b.z + a.w * b.w;
}

__global__ void __launch_bounds__(RDIM) gru_kernel(const float* __restrict__ Q0,
                                                   const float* __restrict__ Wh,
                                                   const float* __restrict__ Uh) {
    const int c    = blockIdx.x;
    const int tid  = threadIdx.x;
    const int warp = tid >> 5;
    const int lane = tid & 31;

    __shared__ float q[RDIM];
    __shared__ float rq[RDIM];

    q[tid] = Q0[tid * CDIM + c];
    __syncthreads();

    const float4* Mz4 = (const float4*)g_Mz;
    const float4* Mr4 = (const float4*)g_Mr;
    const float4* Wh4 = (const float4*)Wh;
    const float4* Uh4 = (const float4*)Uh;

    for (int t = 0; t < TSTEPS; t++) {
        float4 qa = *(const float4*)&q[lane * 8];
        float4 qb = *(const float4*)&q[lane * 8 + 4];

        float sz = 0.f, sr = 0.f;
        #pragma unroll 4
        for (int i = 0; i < 32; i++) {
            int rbase = (warp * 32 + i) * 64 + lane * 2;
            float pz = dot4(Mz4[rbase], qa) + dot4(Mz4[rbase + 1], qb);
            float pr = dot4(Mr4[rbase], qa) + dot4(Mr4[rbase + 1], qb);
            #pragma unroll
            for (int off = 16; off > 0; off >>= 1) {
                pz += __shfl_xor_sync(0xffffffffu, pz, off);
                pr += __shfl_xor_sync(0xffffffffu, pr, off);
            }
            if (lane == i) { sz = pz; sr = pr; }
        }
        float z  = 1.f / (1.f + expf(-sz));
        float rg = 1.f / (1.f + expf(-sr));

        rq[tid] = rg * q[tid];
        __syncthreads();

        float4 ra = *(const float4*)&rq[lane * 8];
        float4 rb = *(const float4*)&rq[lane * 8 + 4];

        float sh = 0.f;
        #pragma unroll 4
        for (int i = 0; i < 32; i++) {
            int rbase = (warp * 32 + i) * 64 + lane * 2;
            float ph = dot4(Wh4[rbase], qa) + dot4(Wh4[rbase + 1], qb)
                     + dot4(Uh4[rbase], ra) + dot4(Uh4[rbase + 1], rb);
            #pragma unroll
            for (int off = 16; off > 0; off >>= 1)
                ph += __shfl_xor_sync(0xffffffffu, ph, off);
            if (lane == i) sh = ph;
        }
        float h  = tanhf(sh);
        float qn = (1.f - z) * q[tid] + z * h;

        __syncthreads();
        q[tid] = qn;
        g_QT[t * RDIM * CDIM + tid * CDIM + c] = qn;
        __syncthreads();
    }
}

// ---------------------------------------------------------------------------
// Packed fp32x2 FMA helpers (used by SIMT XQ gemm)
// ---------------------------------------------------------------------------
__device__ __forceinline__ void ffma2(unsigned long long& d, unsigned long long a,
                                      unsigned long long b) {
    asm("fma.rn.f32x2 %0, %1, %2, %0;" : "+l"(d) : "l"(a), "l"(b));
}
__device__ __forceinline__ unsigned long long splat2(float x) {
    unsigned long long r;
    asm("mov.b64 %0, {%1, %1};" : "=l"(r) : "f"(x));
    return r;
}

// ---------------------------------------------------------------------------
// XQ: Y_t = X_t @ Q_t  (M=4096, K=256, N=32); SIMT f32x2 kernel.
// Epilogue writes Y TRANSPOSED as bf16 hi/lo into g_Yth/g_Ytl [t][n][k=node],
// exactly the B-operand layout the tensor AY kernel consumes.
// ---------------------------------------------------------------------------
__global__ void __launch_bounds__(128) gemm_xq(const float* __restrict__ Xbase,
                                               const float* __restrict__ Qbase) {
    __shared__ float As[2][32][132];
    __shared__ float Bs[2][32][32];

    const int t   = blockIdx.y;
    const int tid = threadIdx.x;
    const int K   = RDIM;
    const float* A = Xbase + (long)t * NNODES * RDIM + (long)blockIdx.x * 128 * K;
    const float* B = Qbase + (long)t * RDIM * CDIM;

    float4 aReg[8];
    float4 bReg[2];
    const int nt = K >> 5;   // 8

    auto loadT = [&](int kt) {
        #pragma unroll
        for (int i = 0; i < 8; i++) {
            int idx = tid + i * 128;
            int m   = idx >> 3;
            int k4  = idx & 7;
            aReg[i] = *(const float4*)(A + (long)m * K + kt * 32 + k4 * 4);
        }
        #pragma unroll
        for (int i = 0; i < 2; i++) {
            int idx = tid + i * 128;
            int kr  = idx >> 3;
            int c4  = idx & 7;
            bReg[i] = *(const float4*)(B + (long)(kt * 32 + kr) * CDIM + c4 * 4);
        }
    };
    auto storeT = [&](int buf) {
        #pragma unroll
        for (int i = 0; i < 8; i++) {
            int idx = tid + i * 128;
            int m   = idx >> 3;
            int k4  = (idx & 7) * 4;
            As[buf][k4 + 0][m] = aReg[i].x;
            As[buf][k4 + 1][m] = aReg[i].y;
            As[buf][k4 + 2][m] = aReg[i].z;
            As[buf][k4 + 3][m] = aReg[i].w;
        }
        #pragma unroll
        for (int i = 0; i < 2; i++) {
            int idx = tid + i * 128;
            int kr  = idx >> 3;
            int c4  = (idx & 7) * 4;
            *(float4*)&Bs[buf][kr][c4] = bReg[i];
        }
    };

    unsigned long long acc[16];
    #pragma unroll
    for (int i = 0; i < 16; i++) acc[i] = 0ull;

    const int m0 = (tid >> 3) * 8;
    const int n0 = (tid & 7) * 4;

    loadT(0);
    storeT(0);
    __syncthreads();

    for (int kt = 0; kt < nt; kt++) {
        int buf = kt & 1;
        if (kt + 1 < nt) loadT(kt + 1);

        #pragma unroll
        for (int k = 0; k < 32; k++) {
            ulonglong2 A0 = *(const ulonglong2*)&As[buf][k][m0];
            ulonglong2 A1 = *(const ulonglong2*)&As[buf][k][m0 + 4];
            float4 bv = *(const float4*)&Bs[buf][k][n0];
            unsigned long long b0 = splat2(bv.x), b1 = splat2(bv.y);
            unsigned long long b2 = splat2(bv.z), b3 = splat2(bv.w);
            ffma2(acc[ 0], A0.x, b0); ffma2(acc[ 1], A0.x, b1);
            ffma2(acc[ 2], A0.x, b2); ffma2(acc[ 3], A0.x, b3);
            ffma2(acc[ 4], A0.y, b0); ffma2(acc[ 5], A0.y, b1);
            ffma2(acc[ 6], A0.y, b2); ffma2(acc[ 7], A0.y, b3);
            ffma2(acc[ 8], A1.x, b0); ffma2(acc[ 9], A1.x, b1);
            ffma2(acc[10], A1.x, b2); ffma2(acc[11], A1.x, b3);
            ffma2(acc[12], A1.y, b0); ffma2(acc[13], A1.y, b1);
            ffma2(acc[14], A1.y, b2); ffma2(acc[15], A1.y, b3);
        }

        if (kt + 1 < nt) {
            __syncthreads();
            storeT(buf ^ 1);
            __syncthreads();
        }
    }

    // Epilogue: split fp32 -> bf16 hi+lo and write transposed [t][n][m]
    const int mglob = blockIdx.x * 128 + m0;
    #pragma unroll
    for (int nj = 0; nj < 4; nj++) {
        float v[8];
        #pragma unroll
        for (int mp = 0; mp < 4; mp++) {
            float2 w = *(float2*)&acc[mp * 4 + nj];
            v[2 * mp]     = w.x;
            v[2 * mp + 1] = w.y;
        }
        uint32_t hp[4], lp[4];
        #pragma unroll
        for (int j = 0; j < 4; j++) {
            hp[j] = cvt_bf16x2(v[2 * j + 1], v[2 * j]);
            float g0 = __uint_as_float(hp[j] << 16);
            float g1 = __uint_as_float(hp[j] & 0xFFFF0000u);
            lp[j] = cvt_bf16x2(v[2 * j + 1] - g1, v[2 * j] - g0);
        }
        long off = ((long)(t * CDIM + n0 + nj)) * NNODES + mglob;  // ushort units
        *(uint4*)(g_Yth + off) = make_uint4(hp[0], hp[1], hp[2], hp[3]);
        *(uint4*)(g_Ytl + off) = make_uint4(lp[0], lp[1], lp[2], lp[3]);
    }
}

// ---------------------------------------------------------------------------
// AY: out_t = relu(A_t @ Y_t) via mma.sync bf16 split-precision (HMMA pipe).
// CTA: 128 rows x 32 cols, K=4096 in 64-wide chunks. 8 warps x (16m x 32n).
// A converted fp32 -> bf16 hi/lo on the fly. 3 terms/k-step:
// Ahi*Bhi + Ahi*Blo + Alo*Bhi (lo*lo dropped, ~2^-18 rel).
// smem rows padded to 72 bf16 (144B): 144 mod 128 = 16 -> ldmatrix 8-row
// fetches hit 8 distinct 16B banks (conflict-free).
// ---------------------------------------------------------------------------
#define AY_NC 64
#define AY_KC 64
#define APAD  72

__global__ void __launch_bounds__(256, 2) ay_mma(const float* __restrict__ A,
                                                 float* __restrict__ Out) {
    __shared__ __align__(16) unsigned short sAh[128 * APAD];
    __shared__ __align__(16) unsigned short sAl[128 * APAD];
    __shared__ __align__(16) unsigned short sBh[32 * APAD];
    __shared__ __align__(16) unsigned short sBl[32 * APAD];

    const int tid  = threadIdx.x;
    const int wid  = tid >> 5;
    const int lane = tid & 31;
    const int t    = blockIdx.y;
    const int mb   = blockIdx.x;

    const float* Ap = A + ((long)t * NNODES + (long)mb * 128) * NNODES;
    const unsigned short* Bgh = g_Yth + (long)t * CDIM * NNODES;
    const unsigned short* Bgl = g_Ytl + (long)t * CDIM * NNODES;

    // Gmem mapping: A 128x64 fp32 = 2048 float4; 8 per thread
    int aoff[8];
    int smA[8];   // bf16-unit offsets into sAh/sAl
    #pragma unroll
    for (int i = 0; i < 8; i++) {
        int idx = tid + i * 256;
        int m = idx >> 4, q = idx & 15;
        aoff[i] = m * NNODES + q * 4;
        smA[i]  = m * APAD + q * 4;
    }
    // B 32x64 bf16 per buffer = 256 uint4; 1 per thread per buffer
    const int bn = tid >> 3, bq = tid & 7;
    const long boff = (long)bn * NNODES + bq * 8;   // ushort units
    const int  smB  = bn * APAD + bq * 8;

    // ldmatrix lane addresses (byte offsets added to smem bases)
    const uint32_t baseAh = smem_u32(sAh), baseAl = smem_u32(sAl);
    const uint32_t baseBh = smem_u32(sBh), baseBl = smem_u32(sBl);
    const int g = lane >> 3;
    // A x4: g0: m0-7 k0 | g1: m8-15 k0 | g2: m0-7 k8 | g3: m8-15 k8
    const int rowA = wid * 16 + (lane & 7) + ((g & 1) ? 8 : 0);
    const uint32_t offA = rowA * (APAD * 2) + (g >> 1) * 16;
    // B x4: g0: n0-7 k0 | g1: n0-7 k8 | g2: n8-15 k0 | g3: n8-15 k8
    const int rowB = (lane & 7) + ((g >> 1) ? 8 : 0);
    const uint32_t offB0 = rowB * (APAD * 2) + (g & 1) * 16;            // n 0-15
    const uint32_t offB1 = (rowB + 16) * (APAD * 2) + (g & 1) * 16;     // n 16-31

    float acc[4][4];
    #pragma unroll
    for (int j = 0; j < 4; j++)
        #pragma unroll
        for (int i = 0; i < 4; i++) acc[j][i] = 0.f;

    float4 aR[8];
    uint4  bhR, blR;

    auto stage = [&](int c) {   // regs -> smem (bf16 split for A)
        #pragma unroll
        for (int i = 0; i < 8; i++) {
            float4 f = aR[i];
            uint32_t h01 = cvt_bf16x2(f.y, f.x);
            uint32_t h23 = cvt_bf16x2(f.w, f.z);
            float g0 = __uint_as_float(h01 << 16);
            float g1 = __uint_as_float(h01 & 0xFFFF0000u);
            float g2 = __uint_as_float(h23 << 16);
            float g3 = __uint_as_float(h23 & 0xFFFF0000u);
            uint32_t l01 = cvt_bf16x2(f.y - g1, f.x - g0);
            uint32_t l23 = cvt_bf16x2(f.w - g3, f.z - g2);
            *(uint2*)&sAh[smA[i]] = make_uint2(h01, h23);
            *(uint2*)&sAl[smA[i]] = make_uint2(l01, l23);
        }
        *(uint4*)&sBh[smB] = bhR;
        *(uint4*)&sBl[smB] = blR;
    };
    auto fetch = [&](int c) {   // gmem -> regs
        const float* ap = Ap + c * AY_KC;
        #pragma unroll
        for (int i = 0; i < 8; i++) aR[i] = *(const float4*)(ap + aoff[i]);
        bhR = *(const uint4*)(Bgh + boff + c * AY_KC);
        blR = *(const uint4*)(Bgl + boff + c * AY_KC);
    };

    fetch(0);
    stage(0);
    __syncthreads();

    for (int c = 0; c < AY_NC; c++) {
        if (c + 1 < AY_NC) fetch(c + 1);

        #pragma unroll
        for (int ks = 0; ks < 4; ks++) {
            uint32_t ah[4], al[4], bh[8], bl[8];
            ldsm4(ah,     baseAh + offA  + ks * 32);
            ldsm4(al,     baseAl + offA  + ks * 32);
            ldsm4(bh,     baseBh + offB0 + ks * 32);
            ldsm4(bh + 4, baseBh + offB1 + ks * 32);
            ldsm4(bl,     baseBl + offB0 + ks * 32);
            ldsm4(bl + 4, baseBl + offB1 + ks * 32);
            #pragma unroll
            for (int j = 0; j < 4; j++) {
                mma16816(acc[j], ah, bh[2 * j], bh[2 * j + 1]);
                mma16816(acc[j], ah, bl[2 * j], bl[2 * j + 1]);
                mma16816(acc[j], al, bh[2 * j], bh[2 * j + 1]);
            }
        }
        __syncthreads();
        if (c + 1 < AY_NC) {
            stage(c + 1);
            __syncthreads();
        }
    }

    // Epilogue: c-frag -> relu -> gmem
    const int cg = lane >> 2;          // group row
    const int tc = (lane & 3) * 2;     // col pair base
    const long row0 = (long)t * NNODES + mb * 128 + wid * 16 + cg;
    #pragma unroll
    for (int j = 0; j < 4; j++) {
        float2 v0, v1;
        v0.x = fmaxf(acc[j][0], 0.f);
        v0.y = fmaxf(acc[j][1], 0.f);
        v1.x = fmaxf(acc[j][2], 0.f);
        v1.y = fmaxf(acc[j][3], 0.f);
        *(float2*)(Out + row0 * CDIM + j * 8 + tc)             = v0;
        *(float2*)(Out + (row0 + 8) * CDIM + j * 8 + tc)       = v1;
    }
}

// ---------------------------------------------------------------------------
// Launch: prep -> GRU -> XQ (bf16 transposed Y) -> AY (mma.sync)
// ---------------------------------------------------------------------------
extern "C" void kernel_launch(void* const* d_in, const int* in_sizes, int n_in,
                              void* d_out, int out_size) {
    const float* A  = (const float*)d_in[0];   // [1,16,4096,4096]
    const float* X  = (const float*)d_in[1];   // [16,4096,256]
    const float* Q0 = (const float*)d_in[2];   // [256,32]
    const float* Wz = (const float*)d_in[3];
    const float* Uz = (const float*)d_in[4];
    const float* Wr = (const float*)d_in[5];
    const float* Ur = (const float*)d_in[6];
    const float* Wh = (const float*)d_in[7];
    const float* Uh = (const float*)d_in[8];
    float* out = (float*)d_out;                // [16,4096,32]

    void* pQT = nullptr;
    cudaGetSymbolAddress(&pQT, g_QT);

    // 1. Fold z/r gate weights
    prep_fold<<<RDIM * RDIM / 256, 256>>>(Wz, Uz, Wr, Ur);

    // 2. Evolve Q over 16 steps (column-parallel, coalesced matvecs)
    gru_kernel<<<CDIM, RDIM>>>(Q0, Wh, Uh);

    // 3. Y_t = X_t @ Q_t -> transposed bf16 hi/lo
    gemm_xq<<<dim3(NNODES / 128, TSTEPS), 128>>>(X, (const float*)pQT);

    // 4. out_t = relu(A_t @ Y_t) via mma.sync tensor cores
    ay_mma<<<dim3(NNODES / 128, TSTEPS), 256>>>(A, out);
}

// round 8
// speedup vs baseline: 3.7957x; 1.0411x over previous
#include <cuda_runtime.h>
#include <cuda_bf16.h>
#include <cstdint>
#include <math.h>

// Problem dims (fixed by dataset)
#define TSTEPS 16
#define NNODES 4096
#define RDIM   256
#define CDIM   32

// Scratch (static device globals — no allocation)
__device__ float g_Mz[RDIM * RDIM];                       // Wz + Uz
__device__ float g_Mr[RDIM * RDIM];                       // Wr + Ur
__device__ unsigned short g_Qth[TSTEPS * CDIM * RDIM];    // Q^T hi bf16 [t][n][k]
__device__ unsigned short g_Qtl[TSTEPS * CDIM * RDIM];    // Q^T lo bf16
__device__ unsigned short g_Yth[TSTEPS * CDIM * NNODES];  // Y^T hi bf16 [t][n][k]
__device__ unsigned short g_Ytl[TSTEPS * CDIM * NNODES];  // Y^T lo bf16

// ---------------------------------------------------------------------------
// Small PTX helpers
// ---------------------------------------------------------------------------
__device__ __forceinline__ uint32_t smem_u32(const void* p) {
    uint32_t a;
    asm("{ .reg .u64 t; cvta.to.shared.u64 t, %1; cvt.u32.u64 %0, t; }"
        : "=r"(a) : "l"(p));
    return a;
}
__device__ __forceinline__ uint32_t cvt_bf16x2(float hi, float lo) {
    uint32_t r;
    asm("cvt.rn.bf16x2.f32 %0, %1, %2;" : "=r"(r) : "f"(hi), "f"(lo));
    return r;
}
__device__ __forceinline__ void ldsm4(uint32_t* r, uint32_t a) {
    asm volatile("ldmatrix.sync.aligned.m8n8.x4.shared.b16 {%0,%1,%2,%3}, [%4];"
                 : "=r"(r[0]), "=r"(r[1]), "=r"(r[2]), "=r"(r[3]) : "r"(a));
}
__device__ __forceinline__ void mma16816(float* c, const uint32_t* a,
                                         uint32_t b0, uint32_t b1) {
    asm volatile(
        "mma.sync.aligned.m16n8k16.row.col.f32.bf16.bf16.f32 "
        "{%0,%1,%2,%3}, {%4,%5,%6,%7}, {%8,%9}, {%0,%1,%2,%3};"
        : "+f"(c[0]), "+f"(c[1]), "+f"(c[2]), "+f"(c[3])
        : "r"(a[0]), "r"(a[1]), "r"(a[2]), "r"(a[3]), "r"(b0), "r"(b1));
}

// ---------------------------------------------------------------------------
// Prep: fold gate weight pairs (z and r gates use W@Q + U@Q = (W+U)@Q)
// ---------------------------------------------------------------------------
__global__ void prep_fold(const float* __restrict__ Wz, const float* __restrict__ Uz,
                          const float* __restrict__ Wr, const float* __restrict__ Ur) {
    int i = blockIdx.x * blockDim.x + threadIdx.x;
    g_Mz[i] = Wz[i] + Uz[i];
    g_Mr[i] = Wr[i] + Ur[i];
}

// ---------------------------------------------------------------------------
// GRU evolution of Q [256,32] over 16 steps. Block = one column.
// Coalesced warp-per-row matvecs with shfl reduction. Emits Q^T bf16 hi/lo
// directly (the B-operand layout the XQ tensor kernel consumes).
// ---------------------------------------------------------------------------
__device__ __forceinline__ float dot4(float4 a, float4 b) {
    return a.x * b.x + a.y * b.y + a.z * b.z + a.w * b.w;
}

__global__ void __launch_bounds__(RDIM) gru_kernel(const float* __restrict__ Q0,
                                                   const float* __restrict__ Wh,
                                                   const float* __restrict__ Uh) {
    const int c    = blockIdx.x;
    const int tid  = threadIdx.x;
    const int warp = tid >> 5;
    const int lane = tid & 31;

    __shared__ float q[RDIM];
    __shared__ float rq[RDIM];

    q[tid] = Q0[tid * CDIM + c];
    __syncthreads();

    const float4* Mz4 = (const float4*)g_Mz;
    const float4* Mr4 = (const float4*)g_Mr;
    const float4* Wh4 = (const float4*)Wh;
    const float4* Uh4 = (const float4*)Uh;

    for (int t = 0; t < TSTEPS; t++) {
        float4 qa = *(const float4*)&q[lane * 8];
        float4 qb = *(const float4*)&q[lane * 8 + 4];

        float sz = 0.f, sr = 0.f;
        #pragma unroll 4
        for (int i = 0; i < 32; i++) {
            int rbase = (warp * 32 + i) * 64 + lane * 2;
            float pz = dot4(Mz4[rbase], qa) + dot4(Mz4[rbase + 1], qb);
            float pr = dot4(Mr4[rbase], qa) + dot4(Mr4[rbase + 1], qb);
            #pragma unroll
            for (int off = 16; off > 0; off >>= 1) {
                pz += __shfl_xor_sync(0xffffffffu, pz, off);
                pr += __shfl_xor_sync(0xffffffffu, pr, off);
            }
            if (lane == i) { sz = pz; sr = pr; }
        }
        float z  = 1.f / (1.f + expf(-sz));
        float rg = 1.f / (1.f + expf(-sr));

        rq[tid] = rg * q[tid];
        __syncthreads();

        float4 ra = *(const float4*)&rq[lane * 8];
        float4 rb = *(const float4*)&rq[lane * 8 + 4];

        float sh = 0.f;
        #pragma unroll 4
        for (int i = 0; i < 32; i++) {
            int rbase = (warp * 32 + i) * 64 + lane * 2;
            float ph = dot4(Wh4[rbase], qa) + dot4(Wh4[rbase + 1], qb)
                     + dot4(Uh4[rbase], ra) + dot4(Uh4[rbase + 1], rb);
            #pragma unroll
            for (int off = 16; off > 0; off >>= 1)
                ph += __shfl_xor_sync(0xffffffffu, ph, off);
            if (lane == i) sh = ph;
        }
        float h  = tanhf(sh);
        float qn = (1.f - z) * q[tid] + z * h;

        __syncthreads();
        q[tid] = qn;
        // Q^T bf16 hi/lo: [t][n=c][k=row]
        uint32_t ph = cvt_bf16x2(0.f, qn);
        float    hf = __uint_as_float(ph << 16);
        uint32_t pl = cvt_bf16x2(0.f, qn - hf);
        long qoff = ((long)t * CDIM + c) * RDIM + tid;
        g_Qth[qoff] = (unsigned short)(ph & 0xFFFFu);
        g_Qtl[qoff] = (unsigned short)(pl & 0xFFFFu);
        __syncthreads();
    }
}

// ---------------------------------------------------------------------------
// Unified tensor GEMM: D[128m x 32n] = A[t] @ B[t]^T  (per-(mb,t) CTA)
//   A: fp32 [4096 x K] row-major, converted to bf16 hi/lo on the fly
//   B: bf16 hi/lo [32 x K] row-major (= B^T operand, col-major for MMA)
//   3 split-precision terms: Ah*Bh + Ah*Bl + Al*Bh
// 128 threads = 4 warps x (32m x 32n). K consumed in 64-wide chunks.
// TRANS_OUT=false: Out[t][m][n] = relu(D)      (the AY phase)
// TRANS_OUT=true : OutT hi/lo [t][n][m] bf16   (the XQ phase -> feeds AY's B)
// smem rows padded to 72 bf16 (144B): conflict-free ldmatrix.
// ---------------------------------------------------------------------------
#define APAD 72
#define SM_AH 0
#define SM_AL (128 * APAD * 2)
#define SM_BH (2 * 128 * APAD * 2)
#define SM_BL (2 * 128 * APAD * 2 + 32 * APAD * 2)
#define SM_TOT (2 * 128 * APAD * 2 + 2 * 32 * APAD * 2)

template<int NC, bool TRANS_OUT>
__global__ void __launch_bounds__(128, 3) mma_gemm(
    const float* __restrict__ Abase,
    const unsigned short* __restrict__ Bhb,
    const unsigned short* __restrict__ Blb,
    float* __restrict__ Out,
    unsigned short* __restrict__ OTh,
    unsigned short* __restrict__ OTl) {

    constexpr int K = NC * 64;
    __shared__ __align__(16) unsigned char smem[SM_TOT];

    const int tid  = threadIdx.x;
    const int wid  = tid >> 5;
    const int lane = tid & 31;
    const int t    = blockIdx.y;
    const int mb   = blockIdx.x;

    const float* Ap = Abase + ((long)t * NNODES + (long)mb * 128) * K;
    const unsigned short* Bgh = Bhb + (long)t * CDIM * K;
    const unsigned short* Bgl = Blb + (long)t * CDIM * K;

    // Gmem A mapping: 128x64 fp32 = 2048 float4; 16 per thread
    int aoff[16];
    int smA[16];   // byte offsets
    #pragma unroll
    for (int i = 0; i < 16; i++) {
        int idx = tid + i * 128;
        int m = idx >> 4, qd = idx & 15;
        aoff[i] = m * K + qd * 4;
        smA[i]  = (m * APAD + qd * 4) * 2;
    }
    // B mapping: 32x64 bf16 per buffer = 256 uint4; 2 per thread
    int boffB[2], smB[2];
    #pragma unroll
    for (int i = 0; i < 2; i++) {
        int idx = tid + i * 128;
        int bn = idx >> 3, bq = idx & 7;
        boffB[i] = bn * K + bq * 8;     // ushort units
        smB[i]   = (bn * APAD + bq * 8) * 2;
    }

    const uint32_t sb = smem_u32(smem);
    const int g = lane >> 3;
    const int rowA = wid * 32 + (lane & 7) + ((g & 1) ? 8 : 0);
    const uint32_t offA0 = rowA * (APAD * 2) + (g >> 1) * 16;
    const uint32_t offA1 = offA0 + 16 * (APAD * 2);
    const int rowB = (lane & 7) + ((g >> 1) ? 8 : 0);
    const uint32_t offB0 = rowB * (APAD * 2) + (g & 1) * 16;
    const uint32_t offB1 = offB0 + 16 * (APAD * 2);

    float acc[2][4][4];
    #pragma unroll
    for (int ti = 0; ti < 2; ti++)
        #pragma unroll
        for (int j = 0; j < 4; j++)
            #pragma unroll
            for (int i = 0; i < 4; i++) acc[ti][j][i] = 0.f;

    float4 aR[16];
    uint4  bhR[2], blR[2];

    auto fetch = [&](int c) {
        const float* ap = Ap + c * 64;
        #pragma unroll
        for (int i = 0; i < 16; i++) aR[i] = *(const float4*)(ap + aoff[i]);
        #pragma unroll
        for (int i = 0; i < 2; i++) {
            bhR[i] = *(const uint4*)(Bgh + boffB[i] + c * 64);
            blR[i] = *(const uint4*)(Bgl + boffB[i] + c * 64);
        }
    };
    auto stage = [&]() {
        #pragma unroll
        for (int i = 0; i < 16; i++) {
            float4 f = aR[i];
            uint32_t h01 = cvt_bf16x2(f.y, f.x);
            uint32_t h23 = cvt_bf16x2(f.w, f.z);
            float g0 = __uint_as_float(h01 << 16);
            float g1 = __uint_as_float(h01 & 0xFFFF0000u);
            float g2 = __uint_as_float(h23 << 16);
            float g3 = __uint_as_float(h23 & 0xFFFF0000u);
            uint32_t l01 = cvt_bf16x2(f.y - g1, f.x - g0);
            uint32_t l23 = cvt_bf16x2(f.w - g3, f.z - g2);
            *(uint2*)(smem + SM_AH + smA[i]) = make_uint2(h01, h23);
            *(uint2*)(smem + SM_AL + smA[i]) = make_uint2(l01, l23);
        }
        #pragma unroll
        for (int i = 0; i < 2; i++) {
            *(uint4*)(smem + SM_BH + smB[i]) = bhR[i];
            *(uint4*)(smem + SM_BL + smB[i]) = blR[i];
        }
    };

    fetch(0);
    stage();
    __syncthreads();

    for (int c = 0; c < NC; c++) {
        if (c + 1 < NC) fetch(c + 1);

        #pragma unroll
        for (int ks = 0; ks < 4; ks++) {
            uint32_t ah0[4], al0[4], ah1[4], al1[4], bh[8], bl[8];
            ldsm4(ah0, sb + SM_AH + offA0 + ks * 32);
            ldsm4(ah1, sb + SM_AH + offA1 + ks * 32);
            ldsm4(al0, sb + SM_AL + offA0 + ks * 32);
            ldsm4(al1, sb + SM_AL + offA1 + ks * 32);
            ldsm4(bh,     sb + SM_BH + offB0 + ks * 32);
            ldsm4(bh + 4, sb + SM_BH + offB1 + ks * 32);
            ldsm4(bl,     sb + SM_BL + offB0 + ks * 32);
            ldsm4(bl + 4, sb + SM_BL + offB1 + ks * 32);
            #pragma unroll
            for (int j = 0; j < 4; j++) {
                mma16816(acc[0][j], ah0, bh[2 * j], bh[2 * j + 1]);
                mma16816(acc[0][j], ah0, bl[2 * j], bl[2 * j + 1]);
                mma16816(acc[0][j], al0, bh[2 * j], bh[2 * j + 1]);
                mma16816(acc[1][j], ah1, bh[2 * j], bh[2 * j + 1]);
                mma16816(acc[1][j], ah1, bl[2 * j], bl[2 * j + 1]);
                mma16816(acc[1][j], al1, bh[2 * j], bh[2 * j + 1]);
            }
        }
        __syncthreads();
        if (c + 1 < NC) {
            stage();
            __syncthreads();
        }
    }

    const int cg = lane >> 2;        // frag row within m8 group
    const int tc = (lane & 3) * 2;   // frag col pair base

    if (!TRANS_OUT) {
        // relu + direct store [t][m][n]
        #pragma unroll
        for (int ti = 0; ti < 2; ti++) {
            const long row0 = (long)t * NNODES + mb * 128 + wid * 32 + ti * 16 + cg;
            #pragma unroll
            for (int j = 0; j < 4; j++) {
                float2 v0, v1;
                v0.x = fmaxf(acc[ti][j][0], 0.f);
                v0.y = fmaxf(acc[ti][j][1], 0.f);
                v1.x = fmaxf(acc[ti][j][2], 0.f);
                v1.y = fmaxf(acc[ti][j][3], 0.f);
                *(float2*)(Out + row0 * CDIM + j * 8 + tc)       = v0;
                *(float2*)(Out + (row0 + 8) * CDIM + j * 8 + tc) = v1;
            }
        }
    } else {
        // Transpose through smem, split bf16 hi/lo, store [t][n][m]
        float* S = (float*)smem;     // [32][132] fp32 = 16.9 KB (reuse)
        #pragma unroll
        for (int ti = 0; ti < 2; ti++) {
            int m = wid * 32 + ti * 16 + cg;
            #pragma unroll
            for (int j = 0; j < 4; j++) {
                int n = j * 8 + tc;
                S[n * 132 + m]           = acc[ti][j][0];
                S[(n + 1) * 132 + m]     = acc[ti][j][1];
                S[n * 132 + m + 8]       = acc[ti][j][2];
                S[(n + 1) * 132 + m + 8] = acc[ti][j][3];
            }
        }
        __syncthreads();
        const int n  = tid >> 2;
        const int ms = (tid & 3) * 32;
        float v[32];
        #pragma unroll
        for (int i = 0; i < 8; i++)
            *(float4*)&v[i * 4] = *(const float4*)&S[n * 132 + ms + i * 4];
        uint32_t hp[16], lp[16];
        #pragma unroll
        for (int i = 0; i < 16; i++) {
            hp[i] = cvt_bf16x2(v[2 * i + 1], v[2 * i]);
            float g0 = __uint_as_float(hp[i] << 16);
            float g1 = __uint_as_float(hp[i] & 0xFFFF0000u);
            lp[i] = cvt_bf16x2(v[2 * i + 1] - g1, v[2 * i] - g0);
        }
        long ooff = ((long)t * CDIM + n) * NNODES + mb * 128 + ms;  // ushort units
        #pragma unroll
        for (int i = 0; i < 4; i++) {
            *(uint4*)(OTh + ooff + i * 8) =
                make_uint4(hp[4 * i], hp[4 * i + 1], hp[4 * i + 2], hp[4 * i + 3]);
            *(uint4*)(OTl + ooff + i * 8) =
                make_uint4(lp[4 * i], lp[4 * i + 1], lp[4 * i + 2], lp[4 * i + 3]);
        }
    }
}

// ---------------------------------------------------------------------------
// Launch: prep -> GRU (emits Q^T bf16) -> XQ (tensor, emits Y^T bf16) -> AY
// ---------------------------------------------------------------------------
extern "C" void kernel_launch(void* const* d_in, const int* in_sizes, int n_in,
                              void* d_out, int out_size) {
    const float* A  = (const float*)d_in[0];   // [1,16,4096,4096]
    const float* X  = (const float*)d_in[1];   // [16,4096,256]
    const float* Q0 = (const float*)d_in[2];   // [256,32]
    const float* Wz = (const float*)d_in[3];
    const float* Uz = (const float*)d_in[4];
    const float* Wr = (const float*)d_in[5];
    const float* Ur = (const float*)d_in[6];
    const float* Wh = (const float*)d_in[7];
    const float* Uh = (const float*)d_in[8];
    float* out = (float*)d_out;                // [16,4096,32]

    void *pQh = nullptr, *pQl = nullptr, *pYh = nullptr, *pYl = nullptr;
    cudaGetSymbolAddress(&pQh, g_Qth);
    cudaGetSymbolAddress(&pQl, g_Qtl);
    cudaGetSymbolAddress(&pYh, g_Yth);
    cudaGetSymbolAddress(&pYl, g_Ytl);

    // 1. Fold z/r gate weights
    prep_fold<<<RDIM * RDIM / 256, 256>>>(Wz, Uz, Wr, Ur);

    // 2. Evolve Q over 16 steps (column-parallel)
    gru_kernel<<<CDIM, RDIM>>>(Q0, Wh, Uh);

    // 3. Y_t = X_t @ Q_t (tensor cores) -> Y^T bf16 hi/lo
    mma_gemm<4, true><<<dim3(NNODES / 128, TSTEPS), 128>>>(
        X, (const unsigned short*)pQh, (const unsigned short*)pQl,
        nullptr, (unsigned short*)pYh, (unsigned short*)pYl);

    // 4. out_t = relu(A_t @ Y_t) (tensor cores)
    mma_gemm<64, false><<<dim3(NNODES / 128, TSTEPS), 128>>>(
        A, (const unsigned short*)pYh, (const unsigned short*)pYl,
        out, nullptr, nullptr);
}